// round 6
// baseline (speedup 1.0000x reference)
#include <cuda_runtime.h>
#include <math.h>

#define N_NODES 50000
#define N_EDGES 800000
#define DIM     64
#define N_LAYERS 5

#define SCAN_BLK  512
#define SCAN_NBLK ((N_NODES + SCAN_BLK - 1) / SCAN_BLK)   // 98

// Scratch (no allocations allowed -> __device__ globals)
__device__ float g_h[N_NODES * DIM];
__device__ float g_pooled[N_LAYERS * DIM];
__device__ int   g_deg[N_NODES];       // degree, then reused as fill cursor
__device__ int   g_off[N_NODES + 1];   // CSR row offsets (by dst)
__device__ int   g_csr[N_EDGES];       // src indices grouped by dst
__device__ int   g_bsum[SCAN_NBLK];    // per-block degree sums

// ---------------------------------------------------------------------------
// Zero: deg = 0, pooled = 0
// ---------------------------------------------------------------------------
__global__ void k_zero()
{
    int i = blockIdx.x * blockDim.x + threadIdx.x;
    if (i < N_NODES) g_deg[i] = 0;
    if (i < N_LAYERS * DIM) g_pooled[i] = 0.0f;
}

// ---------------------------------------------------------------------------
// CSR build step 1: histogram of dst
// ---------------------------------------------------------------------------
__global__ void k_count(const int* __restrict__ dst)
{
    int e = blockIdx.x * blockDim.x + threadIdx.x;
    if (e < N_EDGES)
        atomicAdd(&g_deg[dst[e]], 1);
}

// ---------------------------------------------------------------------------
// CSR scan stage A: per-block sums of degrees
// ---------------------------------------------------------------------------
__global__ void k_scan_a()
{
    __shared__ int sh[SCAN_BLK];
    int tid = threadIdx.x;
    int i = blockIdx.x * SCAN_BLK + tid;
    sh[tid] = (i < N_NODES) ? g_deg[i] : 0;
    __syncthreads();
    for (int o = SCAN_BLK / 2; o > 0; o >>= 1) {
        if (tid < o) sh[tid] += sh[tid + o];
        __syncthreads();
    }
    if (tid == 0) g_bsum[blockIdx.x] = sh[0];
}

// ---------------------------------------------------------------------------
// CSR scan stage C: block offset computed IN-BLOCK (parallel reduce of
// g_bsum[0..blockIdx-1]) + local exclusive scan -> g_off; reset deg.
// (replaces the serial 1-thread k_scan_b that cost ~9us)
// ---------------------------------------------------------------------------
__global__ void k_scan_c()
{
    __shared__ int sh[SCAN_BLK];
    __shared__ int sh2[SCAN_BLK];
    int tid = threadIdx.x;

    // block offset = sum of block sums below us
    sh2[tid] = (tid < blockIdx.x) ? g_bsum[tid] : 0;   // blockIdx.x <= 97 < 512
    __syncthreads();
    for (int o = SCAN_BLK / 2; o > 0; o >>= 1) {
        if (tid < o) sh2[tid] += sh2[tid + o];
        __syncthreads();
    }
    int boff = sh2[0];

    int i = blockIdx.x * SCAN_BLK + tid;
    int v = (i < N_NODES) ? g_deg[i] : 0;
    sh[tid] = v;
    __syncthreads();
    for (int o = 1; o < SCAN_BLK; o <<= 1) {
        int t = (tid >= o) ? sh[tid - o] : 0;
        __syncthreads();
        sh[tid] += t;
        __syncthreads();
    }
    if (i < N_NODES) {
        g_off[i] = boff + (sh[tid] - v);
        g_deg[i] = 0;                           // reset for cursor use
    }
    if (blockIdx.x == 0 && tid == 0) g_off[N_NODES] = N_EDGES;
}

// ---------------------------------------------------------------------------
// CSR build step 3: bucket-fill src indices by dst
// ---------------------------------------------------------------------------
__global__ void k_fill(const int* __restrict__ src, const int* __restrict__ dst)
{
    int e = blockIdx.x * blockDim.x + threadIdx.x;
    if (e < N_EDGES) {
        int d = dst[e];
        int p = atomicAdd(&g_deg[d], 1);
        g_csr[g_off[d] + p] = src[e];
    }
}

// ---------------------------------------------------------------------------
// Fused layer: CSR gather + 3-stage MLP + h writeback + pooled accumulation.
// Block = 128 threads = 2 groups of 64; each group handles NB=16 nodes.
// Gather: thread (g,t) owns feature t of its 16 nodes; 64 lanes reading one
// h row = 256B coalesced. Lands directly in the [k][n] smem layout.
// MLP: packed f32x2 accumulators -> 8 FFMA2 per k => FMA-bound.
// ---------------------------------------------------------------------------
#define NB  16
#define NBP 20
#define GROUPS 2
#define NODES_PER_BLOCK (GROUPS * NB)

__global__ __launch_bounds__(128) void k_layer(const float* __restrict__ x,
                                               const float* __restrict__ W,
                                               int layer, int use_x)
{
    __shared__ __align__(16) float Ws[DIM * DIM];                 // 16 KB
    __shared__ __align__(16) float bufA[GROUPS * DIM * NBP];      // 10 KB
    __shared__ __align__(16) float bufB[GROUPS * DIM * NBP];      // 10 KB
    __shared__ float poolsh[DIM];

    int tid = threadIdx.x;
    int g   = tid >> 6;
    int t   = tid & 63;
    int base = blockIdx.x * NODES_PER_BLOCK + g * NB;

    const float* hsrc = use_x ? x : g_h;

    // ---- Gather phase: acc[n] = h[node][t] + sum_{u in N(node)} h[u][t] ----
#pragma unroll
    for (int n = 0; n < NB; n++) {
        int node = base + n;
        float a = 0.0f, a2 = 0.0f;
        if (node < N_NODES) {
            a = hsrc[node * DIM + t];
            int j   = g_off[node];
            int end = g_off[node + 1];
            for (; j + 2 <= end; j += 2) {
                int u0 = g_csr[j];
                int u1 = g_csr[j + 1];
                a  += hsrc[u0 * DIM + t];
                a2 += hsrc[u1 * DIM + t];
            }
            if (j < end)
                a += hsrc[g_csr[j] * DIM + t];
        }
        bufA[(g * DIM + t) * NBP + n] = a + a2;
    }
    if (tid < DIM) poolsh[tid] = 0.0f;

    const float* Wbase = W + (size_t)layer * 3 * DIM * DIM;

    float* inb  = bufA;
    float* outb = bufB;
    float psum = 0.0f;

    for (int s = 0; s < 3; s++) {
        __syncthreads();
        const float4* Wst = reinterpret_cast<const float4*>(Wbase + s * DIM * DIM);
        float4* Wsv = reinterpret_cast<float4*>(Ws);
#pragma unroll
        for (int i = 0; i < DIM * DIM / 4 / 128; i++)
            Wsv[i * 128 + tid] = Wst[i * 128 + tid];
        __syncthreads();

        unsigned long long acc0 = 0ull, acc1 = 0ull, acc2 = 0ull, acc3 = 0ull;
        unsigned long long acc4 = 0ull, acc5 = 0ull, acc6 = 0ull, acc7 = 0ull;
        const ulonglong2* in2 =
            reinterpret_cast<const ulonglong2*>(inb + g * DIM * NBP);

#pragma unroll 4
        for (int k = 0; k < DIM; k++) {
            unsigned int wb = __float_as_uint(Ws[k * DIM + t]);
            unsigned long long wp;
            asm("mov.b64 %0, {%1, %1};" : "=l"(wp) : "r"(wb));
            ulonglong2 q0 = in2[k * 5 + 0];
            ulonglong2 q1 = in2[k * 5 + 1];
            ulonglong2 q2 = in2[k * 5 + 2];
            ulonglong2 q3 = in2[k * 5 + 3];
            asm("fma.rn.f32x2 %0, %1, %2, %0;" : "+l"(acc0) : "l"(q0.x), "l"(wp));
            asm("fma.rn.f32x2 %0, %1, %2, %0;" : "+l"(acc1) : "l"(q0.y), "l"(wp));
            asm("fma.rn.f32x2 %0, %1, %2, %0;" : "+l"(acc2) : "l"(q1.x), "l"(wp));
            asm("fma.rn.f32x2 %0, %1, %2, %0;" : "+l"(acc3) : "l"(q1.y), "l"(wp));
            asm("fma.rn.f32x2 %0, %1, %2, %0;" : "+l"(acc4) : "l"(q2.x), "l"(wp));
            asm("fma.rn.f32x2 %0, %1, %2, %0;" : "+l"(acc5) : "l"(q2.y), "l"(wp));
            asm("fma.rn.f32x2 %0, %1, %2, %0;" : "+l"(acc6) : "l"(q3.x), "l"(wp));
            asm("fma.rn.f32x2 %0, %1, %2, %0;" : "+l"(acc7) : "l"(q3.y), "l"(wp));
        }

        float o[NB];
        {
            float2 a;
            a = *reinterpret_cast<float2*>(&acc0); o[0]  = fmaxf(a.x, 0.f); o[1]  = fmaxf(a.y, 0.f);
            a = *reinterpret_cast<float2*>(&acc1); o[2]  = fmaxf(a.x, 0.f); o[3]  = fmaxf(a.y, 0.f);
            a = *reinterpret_cast<float2*>(&acc2); o[4]  = fmaxf(a.x, 0.f); o[5]  = fmaxf(a.y, 0.f);
            a = *reinterpret_cast<float2*>(&acc3); o[6]  = fmaxf(a.x, 0.f); o[7]  = fmaxf(a.y, 0.f);
            a = *reinterpret_cast<float2*>(&acc4); o[8]  = fmaxf(a.x, 0.f); o[9]  = fmaxf(a.y, 0.f);
            a = *reinterpret_cast<float2*>(&acc5); o[10] = fmaxf(a.x, 0.f); o[11] = fmaxf(a.y, 0.f);
            a = *reinterpret_cast<float2*>(&acc6); o[12] = fmaxf(a.x, 0.f); o[13] = fmaxf(a.y, 0.f);
            a = *reinterpret_cast<float2*>(&acc7); o[14] = fmaxf(a.x, 0.f); o[15] = fmaxf(a.y, 0.f);
        }

        float* ob = outb + (g * DIM + t) * NBP;
        reinterpret_cast<float4*>(ob)[0] = make_float4(o[0],  o[1],  o[2],  o[3]);
        reinterpret_cast<float4*>(ob)[1] = make_float4(o[4],  o[5],  o[6],  o[7]);
        reinterpret_cast<float4*>(ob)[2] = make_float4(o[8],  o[9],  o[10], o[11]);
        reinterpret_cast<float4*>(ob)[3] = make_float4(o[12], o[13], o[14], o[15]);

        if (s == 2) {
            float ps = 0.0f;
#pragma unroll
            for (int n = 0; n < NB; n++) {
                int node = base + n;
                if (node < N_NODES) {
                    g_h[node * DIM + t] = o[n];
                    ps += o[n];
                }
            }
            psum = ps;
        }
        float* tmp = inb; inb = outb; outb = tmp;
    }

    __syncthreads();
    atomicAdd(&poolsh[t], psum);
    __syncthreads();
    if (tid < DIM)
        atomicAdd(&g_pooled[layer * DIM + tid], poolsh[tid]);
}

// ---------------------------------------------------------------------------
// Final: out = sigmoid( sum_l dot(pooled_l / N, Wl_l) )
// ---------------------------------------------------------------------------
__global__ void k_final(const float* __restrict__ Wl, float* __restrict__ out)
{
    __shared__ float red[128];
    int tid = threadIdx.x;
    float s = 0.0f;
    for (int i = tid; i < N_LAYERS * DIM; i += 128)
        s += g_pooled[i] * Wl[i];
    red[tid] = s;
    __syncthreads();
    for (int o = 64; o > 0; o >>= 1) {
        if (tid < o) red[tid] += red[tid + o];
        __syncthreads();
    }
    if (tid == 0) {
        float v = red[0] / (float)N_NODES;
        out[0] = 1.0f / (1.0f + expf(-v));
    }
}

// ---------------------------------------------------------------------------
// Launch
// ---------------------------------------------------------------------------
extern "C" void kernel_launch(void* const* d_in, const int* in_sizes, int n_in,
                              void* d_out, int out_size)
{
    const float* x   = (const float*)d_in[0];
    const float* W   = (const float*)d_in[1];
    const float* Wl  = (const float*)d_in[2];
    const int*   src = (const int*)d_in[3];
    const int*   dst = (const int*)d_in[4];
    float*       out = (float*)d_out;

    (void)in_sizes; (void)n_in; (void)out_size;

    // CSR build
    k_zero<<<(N_NODES + 255) / 256, 256>>>();
    k_count<<<(N_EDGES + 255) / 256, 256>>>(dst);
    k_scan_a<<<SCAN_NBLK, SCAN_BLK>>>();
    k_scan_c<<<SCAN_NBLK, SCAN_BLK>>>();
    k_fill<<<(N_EDGES + 255) / 256, 256>>>(src, dst);

    int layer_blocks = (N_NODES + NODES_PER_BLOCK - 1) / NODES_PER_BLOCK;

    for (int l = 0; l < N_LAYERS; l++)
        k_layer<<<layer_blocks, 128>>>(x, W, l, l == 0 ? 1 : 0);

    k_final<<<1, 128>>>(Wl, out);
}

// round 7
// speedup vs baseline: 1.2114x; 1.2114x over previous
#include <cuda_runtime.h>
#include <math.h>

#define N_NODES 50000
#define N_EDGES 800000
#define DIM     64
#define N_LAYERS 5

#define SCAN_BLK  512
#define SCAN_NBLK ((N_NODES + SCAN_BLK - 1) / SCAN_BLK)   // 98

// Scratch (no allocations allowed -> __device__ globals)
__device__ float g_agg[N_NODES * DIM];
__device__ float g_h[N_NODES * DIM];
__device__ float g_pooled[N_LAYERS * DIM];
__device__ int   g_deg[N_NODES];       // degree, then reused as fill cursor
__device__ int   g_off[N_NODES + 1];   // CSR row offsets (by dst)
__device__ int   g_csr[N_EDGES];       // src indices grouped by dst
__device__ int   g_bsum[SCAN_NBLK];    // per-block degree sums

// ---------------------------------------------------------------------------
// Zero: deg = 0, pooled = 0
// ---------------------------------------------------------------------------
__global__ void k_zero()
{
    int i = blockIdx.x * blockDim.x + threadIdx.x;
    if (i < N_NODES) g_deg[i] = 0;
    if (i < N_LAYERS * DIM) g_pooled[i] = 0.0f;
}

// ---------------------------------------------------------------------------
// CSR build step 1: histogram of dst
// ---------------------------------------------------------------------------
__global__ void k_count(const int* __restrict__ dst)
{
    int e = blockIdx.x * blockDim.x + threadIdx.x;
    if (e < N_EDGES)
        atomicAdd(&g_deg[dst[e]], 1);
}

// ---------------------------------------------------------------------------
// CSR scan stage A: per-block sums of degrees
// ---------------------------------------------------------------------------
__global__ void k_scan_a()
{
    __shared__ int sh[SCAN_BLK];
    int tid = threadIdx.x;
    int i = blockIdx.x * SCAN_BLK + tid;
    sh[tid] = (i < N_NODES) ? g_deg[i] : 0;
    __syncthreads();
    for (int o = SCAN_BLK / 2; o > 0; o >>= 1) {
        if (tid < o) sh[tid] += sh[tid + o];
        __syncthreads();
    }
    if (tid == 0) g_bsum[blockIdx.x] = sh[0];
}

// ---------------------------------------------------------------------------
// CSR scan stage C: block offset computed in-block + local exclusive scan
// ---------------------------------------------------------------------------
__global__ void k_scan_c()
{
    __shared__ int sh[SCAN_BLK];
    __shared__ int sh2[SCAN_BLK];
    int tid = threadIdx.x;

    sh2[tid] = (tid < blockIdx.x) ? g_bsum[tid] : 0;
    __syncthreads();
    for (int o = SCAN_BLK / 2; o > 0; o >>= 1) {
        if (tid < o) sh2[tid] += sh2[tid + o];
        __syncthreads();
    }
    int boff = sh2[0];

    int i = blockIdx.x * SCAN_BLK + tid;
    int v = (i < N_NODES) ? g_deg[i] : 0;
    sh[tid] = v;
    __syncthreads();
    for (int o = 1; o < SCAN_BLK; o <<= 1) {
        int t = (tid >= o) ? sh[tid - o] : 0;
        __syncthreads();
        sh[tid] += t;
        __syncthreads();
    }
    if (i < N_NODES) {
        g_off[i] = boff + (sh[tid] - v);
        g_deg[i] = 0;
    }
    if (blockIdx.x == 0 && tid == 0) g_off[N_NODES] = N_EDGES;
}

// ---------------------------------------------------------------------------
// CSR build step 3: bucket-fill src indices by dst
// ---------------------------------------------------------------------------
__global__ void k_fill(const int* __restrict__ src, const int* __restrict__ dst)
{
    int e = blockIdx.x * blockDim.x + threadIdx.x;
    if (e < N_EDGES) {
        int d = dst[e];
        int p = atomicAdd(&g_deg[d], 1);
        g_csr[g_off[d] + p] = src[e];
    }
}

// ---------------------------------------------------------------------------
// Gather: agg[v] = h[v] + sum_{u in N(v)} h[u]   (no atomics)
// 16 threads per node, one float4 chunk each (coalesced 256B row reads).
// Source selected in-kernel (host &g_h = shadow symbol, R3 bug).
// ---------------------------------------------------------------------------
__global__ void k_gather(const float4* __restrict__ x, int use_x)
{
    int idx = blockIdx.x * blockDim.x + threadIdx.x;
    if (idx >= N_NODES * 16) return;
    int v = idx >> 4;
    int c = idx & 15;

    const float4* hsrc = use_x ? x : reinterpret_cast<const float4*>(g_h);

    float4 acc = __ldg(&hsrc[v * 16 + c]);
    float4 s1 = make_float4(0.f, 0.f, 0.f, 0.f);
    float4 s2 = make_float4(0.f, 0.f, 0.f, 0.f);
    float4 s3 = make_float4(0.f, 0.f, 0.f, 0.f);

    int j = g_off[v];
    int end = g_off[v + 1];

    for (; j + 4 <= end; j += 4) {
        int u0 = __ldg(&g_csr[j]);
        int u1 = __ldg(&g_csr[j + 1]);
        int u2 = __ldg(&g_csr[j + 2]);
        int u3 = __ldg(&g_csr[j + 3]);
        float4 a = __ldg(&hsrc[u0 * 16 + c]);
        float4 b = __ldg(&hsrc[u1 * 16 + c]);
        float4 d = __ldg(&hsrc[u2 * 16 + c]);
        float4 e = __ldg(&hsrc[u3 * 16 + c]);
        acc.x += a.x; acc.y += a.y; acc.z += a.z; acc.w += a.w;
        s1.x += b.x;  s1.y += b.y;  s1.z += b.z;  s1.w += b.w;
        s2.x += d.x;  s2.y += d.y;  s2.z += d.z;  s2.w += d.w;
        s3.x += e.x;  s3.y += e.y;  s3.z += e.z;  s3.w += e.w;
    }
    for (; j < end; j++) {
        float4 a = __ldg(&hsrc[__ldg(&g_csr[j]) * 16 + c]);
        acc.x += a.x; acc.y += a.y; acc.z += a.z; acc.w += a.w;
    }
    acc.x += s1.x + s2.x + s3.x;
    acc.y += s1.y + s2.y + s3.y;
    acc.z += s1.z + s2.z + s3.z;
    acc.w += s1.w + s2.w + s3.w;

    reinterpret_cast<float4*>(g_agg)[v * 16 + c] = acc;
}

// ---------------------------------------------------------------------------
// Fused 3-stage MLP (relu x3) + h writeback + pooled-sum accumulation.
// Block = 256 threads = 4 groups of 64; each group handles NB=16 nodes
// (64 nodes/block). 8 warps/block for better latency hiding vs R5's 4.
// Packed f32x2 accumulators -> 8 FFMA2 per k.
// ---------------------------------------------------------------------------
#define NB  16
#define NBP 20
#define GROUPS 4
#define NODES_PER_BLOCK (GROUPS * NB)   // 64

__global__ __launch_bounds__(256) void k_mlp(const float* __restrict__ W, int layer)
{
    __shared__ __align__(16) float Ws[DIM * DIM];                 // 16 KB
    __shared__ __align__(16) float bufA[GROUPS * DIM * NBP];      // 20 KB
    __shared__ __align__(16) float bufB[GROUPS * DIM * NBP];      // 20 KB
    __shared__ float poolsh[DIM];

    int tid = threadIdx.x;
    int g   = tid >> 6;
    int t   = tid & 63;
    int base = blockIdx.x * NODES_PER_BLOCK + g * NB;

#pragma unroll
    for (int n = 0; n < NB; n++) {
        int node = base + n;
        bufA[(g * DIM + t) * NBP + n] = (node < N_NODES) ? g_agg[node * DIM + t] : 0.0f;
    }
    if (tid < DIM) poolsh[tid] = 0.0f;

    const float* Wbase = W + (size_t)layer * 3 * DIM * DIM;

    float* inb  = bufA;
    float* outb = bufB;
    float psum = 0.0f;

    for (int s = 0; s < 3; s++) {
        __syncthreads();
        // Stage weight load: 16 floats per thread (256 threads)
        const float4* Wst = reinterpret_cast<const float4*>(Wbase + s * DIM * DIM);
        float4* Wsv = reinterpret_cast<float4*>(Ws);
#pragma unroll
        for (int i = 0; i < DIM * DIM / 4 / 256; i++)
            Wsv[i * 256 + tid] = Wst[i * 256 + tid];
        __syncthreads();

        unsigned long long acc0 = 0ull, acc1 = 0ull, acc2 = 0ull, acc3 = 0ull;
        unsigned long long acc4 = 0ull, acc5 = 0ull, acc6 = 0ull, acc7 = 0ull;
        const ulonglong2* in2 =
            reinterpret_cast<const ulonglong2*>(inb + g * DIM * NBP);

#pragma unroll 4
        for (int k = 0; k < DIM; k++) {
            unsigned int wb = __float_as_uint(Ws[k * DIM + t]);
            unsigned long long wp;
            asm("mov.b64 %0, {%1, %1};" : "=l"(wp) : "r"(wb));
            ulonglong2 q0 = in2[k * 5 + 0];
            ulonglong2 q1 = in2[k * 5 + 1];
            ulonglong2 q2 = in2[k * 5 + 2];
            ulonglong2 q3 = in2[k * 5 + 3];
            asm("fma.rn.f32x2 %0, %1, %2, %0;" : "+l"(acc0) : "l"(q0.x), "l"(wp));
            asm("fma.rn.f32x2 %0, %1, %2, %0;" : "+l"(acc1) : "l"(q0.y), "l"(wp));
            asm("fma.rn.f32x2 %0, %1, %2, %0;" : "+l"(acc2) : "l"(q1.x), "l"(wp));
            asm("fma.rn.f32x2 %0, %1, %2, %0;" : "+l"(acc3) : "l"(q1.y), "l"(wp));
            asm("fma.rn.f32x2 %0, %1, %2, %0;" : "+l"(acc4) : "l"(q2.x), "l"(wp));
            asm("fma.rn.f32x2 %0, %1, %2, %0;" : "+l"(acc5) : "l"(q2.y), "l"(wp));
            asm("fma.rn.f32x2 %0, %1, %2, %0;" : "+l"(acc6) : "l"(q3.x), "l"(wp));
            asm("fma.rn.f32x2 %0, %1, %2, %0;" : "+l"(acc7) : "l"(q3.y), "l"(wp));
        }

        float o[NB];
        {
            float2 a;
            a = *reinterpret_cast<float2*>(&acc0); o[0]  = fmaxf(a.x, 0.f); o[1]  = fmaxf(a.y, 0.f);
            a = *reinterpret_cast<float2*>(&acc1); o[2]  = fmaxf(a.x, 0.f); o[3]  = fmaxf(a.y, 0.f);
            a = *reinterpret_cast<float2*>(&acc2); o[4]  = fmaxf(a.x, 0.f); o[5]  = fmaxf(a.y, 0.f);
            a = *reinterpret_cast<float2*>(&acc3); o[6]  = fmaxf(a.x, 0.f); o[7]  = fmaxf(a.y, 0.f);
            a = *reinterpret_cast<float2*>(&acc4); o[8]  = fmaxf(a.x, 0.f); o[9]  = fmaxf(a.y, 0.f);
            a = *reinterpret_cast<float2*>(&acc5); o[10] = fmaxf(a.x, 0.f); o[11] = fmaxf(a.y, 0.f);
            a = *reinterpret_cast<float2*>(&acc6); o[12] = fmaxf(a.x, 0.f); o[13] = fmaxf(a.y, 0.f);
            a = *reinterpret_cast<float2*>(&acc7); o[14] = fmaxf(a.x, 0.f); o[15] = fmaxf(a.y, 0.f);
        }

        float* ob = outb + (g * DIM + t) * NBP;
        reinterpret_cast<float4*>(ob)[0] = make_float4(o[0],  o[1],  o[2],  o[3]);
        reinterpret_cast<float4*>(ob)[1] = make_float4(o[4],  o[5],  o[6],  o[7]);
        reinterpret_cast<float4*>(ob)[2] = make_float4(o[8],  o[9],  o[10], o[11]);
        reinterpret_cast<float4*>(ob)[3] = make_float4(o[12], o[13], o[14], o[15]);

        if (s == 2) {
            float ps = 0.0f;
#pragma unroll
            for (int n = 0; n < NB; n++) {
                int node = base + n;
                if (node < N_NODES) {
                    g_h[node * DIM + t] = o[n];
                    ps += o[n];
                }
            }
            psum = ps;
        }
        float* tmp = inb; inb = outb; outb = tmp;
    }

    __syncthreads();
    atomicAdd(&poolsh[t], psum);
    __syncthreads();
    if (tid < DIM)
        atomicAdd(&g_pooled[layer * DIM + tid], poolsh[tid]);
}

// ---------------------------------------------------------------------------
// Final: out = sigmoid( sum_l dot(pooled_l / N, Wl_l) )
// ---------------------------------------------------------------------------
__global__ void k_final(const float* __restrict__ Wl, float* __restrict__ out)
{
    __shared__ float red[128];
    int tid = threadIdx.x;
    float s = 0.0f;
    for (int i = tid; i < N_LAYERS * DIM; i += 128)
        s += g_pooled[i] * Wl[i];
    red[tid] = s;
    __syncthreads();
    for (int o = 64; o > 0; o >>= 1) {
        if (tid < o) red[tid] += red[tid + o];
        __syncthreads();
    }
    if (tid == 0) {
        float v = red[0] / (float)N_NODES;
        out[0] = 1.0f / (1.0f + expf(-v));
    }
}

// ---------------------------------------------------------------------------
// Launch
// ---------------------------------------------------------------------------
extern "C" void kernel_launch(void* const* d_in, const int* in_sizes, int n_in,
                              void* d_out, int out_size)
{
    const float* x   = (const float*)d_in[0];
    const float* W   = (const float*)d_in[1];
    const float* Wl  = (const float*)d_in[2];
    const int*   src = (const int*)d_in[3];
    const int*   dst = (const int*)d_in[4];
    float*       out = (float*)d_out;

    (void)in_sizes; (void)n_in; (void)out_size;

    // CSR build
    k_zero<<<(N_NODES + 255) / 256, 256>>>();
    k_count<<<(N_EDGES + 255) / 256, 256>>>(dst);
    k_scan_a<<<SCAN_NBLK, SCAN_BLK>>>();
    k_scan_c<<<SCAN_NBLK, SCAN_BLK>>>();
    k_fill<<<(N_EDGES + 255) / 256, 256>>>(src, dst);

    int gather_blocks = (N_NODES * 16 + 255) / 256;
    int mlp_blocks    = (N_NODES + NODES_PER_BLOCK - 1) / NODES_PER_BLOCK;

    for (int l = 0; l < N_LAYERS; l++) {
        k_gather<<<gather_blocks, 256>>>((const float4*)x, l == 0 ? 1 : 0);
        k_mlp<<<mlp_blocks, 256>>>(W, l);
    }
    k_final<<<1, 128>>>(Wl, out);
}